// round 9
// baseline (speedup 1.0000x reference)
#include <cuda_runtime.h>
#include <cuda_fp16.h>

#define NV   8
#define C_CH 32
#define H_F  128
#define W_F  128
#define HW_F (H_F * W_F)
#define RESO 64

#define VOXEL_F ((float)(0.3/64.0))
#define HALF_F  ((float)(0.3/128.0))

typedef unsigned long long u64;
typedef unsigned u32;

// ---- packed f32x2 helpers ----
__device__ __forceinline__ u64 pack2(float lo, float hi) {
    u64 r; asm("mov.b64 %0, {%1, %2};" : "=l"(r) : "f"(lo), "f"(hi)); return r;
}
__device__ __forceinline__ float2 unpack2(u64 p) {
    float2 r; asm("mov.b64 {%0, %1}, %2;" : "=f"(r.x), "=f"(r.y) : "l"(p)); return r;
}
__device__ __forceinline__ void ffma2(u64& d, u64 a, u64 b) {
    asm("fma.rn.f32x2 %0, %1, %2, %0;" : "+l"(d) : "l"(a), "l"(b));
}
__device__ __forceinline__ u32 pack_h2(float lo, float hi) {
    u32 r; asm("cvt.rn.f16x2.f32 %0, %1, %2;" : "=r"(r) : "f"(hi), "f"(lo)); return r;
}
__device__ __forceinline__ u32 f32x2_to_f16x2(u64 p) {
    float2 t = unpack2(p);
    return pack_h2(t.x, t.y);
}
__device__ __forceinline__ float rhalf(float x) {
    return __half2float(__float2half_rn(x));
}

// ---- tensor-core helpers ----
__device__ __forceinline__ void ldsm_x4(u32& r0, u32& r1, u32& r2, u32& r3, u32 addr) {
    asm volatile("ldmatrix.sync.aligned.m8n8.x4.shared.b16 {%0,%1,%2,%3}, [%4];"
                 : "=r"(r0), "=r"(r1), "=r"(r2), "=r"(r3) : "r"(addr));
}
__device__ __forceinline__ void mma16816(float* c, const u32* a, u32 b0, u32 b1) {
    asm volatile("mma.sync.aligned.m16n8k16.row.col.f32.f16.f16.f32 "
                 "{%0,%1,%2,%3}, {%4,%5,%6,%7}, {%8,%9}, {%0,%1,%2,%3};"
                 : "+f"(c[0]), "+f"(c[1]), "+f"(c[2]), "+f"(c[3])
                 : "r"(a[0]), "r"(a[1]), "r"(a[2]), "r"(a[3]), "r"(b0), "r"(b1));
}

// Scratch
__device__ __align__(16) u32 g_Gh[4 * NV * HW_F * 4];   // fp16 plane-split G
__device__ float g_msum[NV * RESO * RESO];
__device__ __align__(16) u32 g_frag[7 * 32 * 4];        // per-lane MMA weight/bias frags
__device__ float g_M[NV * 12];                          // per-view projection matrices

#define GEMM_BLOCKS 512
#define MSUM_BLOCKS 128
#define PLANE_BYTES (NV * HW_F * 16)

// ---------------------------------------------------------------------------
// Prep kernel: [0,512) per-pixel GEMM (two passes of 16 outputs to keep regs
// <=64 for 4 blocks/SM); [512,640) msum; block 640 = fragment/M precompute.
// ---------------------------------------------------------------------------
__global__ __launch_bounds__(256, 4)
void prep_kernel(const float* __restrict__ feats,
                 const float* __restrict__ W1,
                 const float* __restrict__ b1,
                 const float* __restrict__ Ks,
                 const float* __restrict__ poses,
                 const float* __restrict__ bbox,
                 const int* __restrict__ ph,
                 const int* __restrict__ pw,
                 const float* __restrict__ W2, const float* __restrict__ b2,
                 const float* __restrict__ W3, const float* __restrict__ b3) {
    int tid = threadIdx.x;
    if (blockIdx.x < GEMM_BLOCKS) {
        __shared__ __align__(16) float sW1[C_CH * C_CH];
        __shared__ __align__(16) float sB1[C_CH];
        for (int t = tid; t < 1024; t += 256) sW1[t] = W1[t];
        if (tid < 32) sB1[tid] = b1[tid];
        __syncthreads();

        int p  = blockIdx.x * 256 + tid;
        int v  = p >> 14;
        int pl = p & (HW_F - 1);
        const float* fp = feats + (size_t)v * C_CH * HW_F + pl;
        uint4* gbase = (uint4*)g_Gh;

#pragma unroll
        for (int half = 0; half < 2; half++) {
            u64 acc[8];
            const u64* sBh = (const u64*)(sB1 + half * 16);
#pragma unroll
            for (int q = 0; q < 8; q++) acc[q] = sBh[q];

#pragma unroll
            for (int c = 0; c < 32; c++) {
                float f = fp[c * HW_F];
                u64 f2 = pack2(f, f);
                const ulonglong2* wr = (const ulonglong2*)(sW1 + c * 32 + half * 16);
#pragma unroll
                for (int j4 = 0; j4 < 4; j4++) {
                    ulonglong2 w = wr[j4];
                    ffma2(acc[j4 * 2 + 0], f2, w.x);
                    ffma2(acc[j4 * 2 + 1], f2, w.y);
                }
            }

#pragma unroll
            for (int pp = 0; pp < 2; pp++) {
                uint4 o;
                o.x = f32x2_to_f16x2(acc[pp * 4 + 0]);
                o.y = f32x2_to_f16x2(acc[pp * 4 + 1]);
                o.z = f32x2_to_f16x2(acc[pp * 4 + 2]);
                o.w = f32x2_to_f16x2(acc[pp * 4 + 3]);
                gbase[(size_t)(half * 2 + pp) * (NV * HW_F) + p] = o;
            }
        }
    } else if (blockIdx.x < GEMM_BLOCKS + MSUM_BLOCKS) {
        int idx = (blockIdx.x - GEMM_BLOCKS) * 256 + tid;   // 0..32767
        int k = idx & 63, j = (idx >> 6) & 63, v = idx >> 12;

        const float* K = Ks + v * 9;
        const float* P = poses + v * 12;
        float M[12];
#pragma unroll
        for (int r = 0; r < 3; r++)
#pragma unroll
            for (int c = 0; c < 4; c++)
                M[r * 4 + c] = K[r * 3 + 0] * P[0 * 4 + c] +
                               K[r * 3 + 1] * P[1 * 4 + c] +
                               K[r * 3 + 2] * P[2 * 4 + c];

        float img_wf = (float)(*pw), img_hf = (float)(*ph);
        float y = (float)j * VOXEL_F + HALF_F + bbox[1];
        float z = (float)k * VOXEL_F + HALF_F + bbox[2];

        float s = 0.f;
        for (int i = 0; i < RESO; i++) {
            float x  = (float)i * VOXEL_F + HALF_F + bbox[0];
            float px = M[0] * x + M[1] * y + M[2]  * z + M[3];
            float py = M[4] * x + M[5] * y + M[6]  * z + M[7];
            float pz = M[8] * x + M[9] * y + M[10] * z + M[11];
            float u  = px / pz, vv = py / pz;
            float gx = u / img_wf - 1.f, gy = vv / img_hf - 1.f;
            float ix = (gx + 1.f) * 0.5f * (float)(W_F - 1);
            float iy = (gy + 1.f) * 0.5f * (float)(H_F - 1);
            float m = (ix >= 0.f && ix <= (float)(W_F - 1) &&
                       iy >= 0.f && iy <= (float)(H_F - 1) && pz > 0.f) ? 1.f : 0.f;
            s += m;
        }
        g_msum[idx] = s;
    } else {
        // fragment + M precompute
        if (tid < 32) {
            int lane = tid;
            int bn = lane >> 2;
            int bk = (lane & 3) * 2;
            u32 fr[28];
#pragma unroll
            for (int kt = 0; kt < 2; kt++)
#pragma unroll
                for (int nt = 0; nt < 2; nt++) {
                    int n = bn + nt * 8;
                    int k0 = bk + kt * 16;
                    float w0 = W2[(k0    ) * 16 + n];
                    float w1 = W2[(k0 + 1) * 16 + n];
                    float w8 = W2[(k0 + 8) * 16 + n];
                    float w9 = W2[(k0 + 9) * 16 + n];
                    fr[    kt * 4 + nt * 2 + 0] = pack_h2(w0, w1);
                    fr[    kt * 4 + nt * 2 + 1] = pack_h2(w8, w9);
                    fr[8 + kt * 4 + nt * 2 + 0] = pack_h2(w0 - rhalf(w0), w1 - rhalf(w1));
                    fr[8 + kt * 4 + nt * 2 + 1] = pack_h2(w8 - rhalf(w8), w9 - rhalf(w9));
                }
            {
                float w0 = W3[(bk    ) * 8 + bn];
                float w1 = W3[(bk + 1) * 8 + bn];
                float w8 = W3[(bk + 8) * 8 + bn];
                float w9 = W3[(bk + 9) * 8 + bn];
                fr[16] = pack_h2(w0, w1);
                fr[17] = pack_h2(w8, w9);
                fr[18] = pack_h2(w0 - rhalf(w0), w1 - rhalf(w1));
                fr[19] = pack_h2(w8 - rhalf(w8), w9 - rhalf(w9));
            }
            fr[20] = __float_as_uint(b2[bk]);
            fr[21] = __float_as_uint(b2[bk + 1]);
            fr[22] = __float_as_uint(b2[8 + bk]);
            fr[23] = __float_as_uint(b2[8 + bk + 1]);
            fr[24] = __float_as_uint(b3[bk]);
            fr[25] = __float_as_uint(b3[bk + 1]);
            fr[26] = 0; fr[27] = 0;
#pragma unroll
            for (int c4 = 0; c4 < 7; c4++)
#pragma unroll
                for (int r = 0; r < 4; r++)
                    g_frag[(c4 * 32 + lane) * 4 + r] = fr[c4 * 4 + r];
        } else if (tid < 128 + 32 && tid >= 32) {
            int e = tid - 32;
            if (e < 96) {
                int v = e / 12, q = e % 12, r = q >> 2, c = q & 3;
                const float* K = Ks + v * 9;
                const float* P = poses + v * 12;
                g_M[e] = K[r * 3 + 0] * P[0 + c] + K[r * 3 + 1] * P[4 + c] +
                         K[r * 3 + 2] * P[8 + c];
            }
        }
    }
}

// ---------------------------------------------------------------------------
// Main fused kernel.
// ---------------------------------------------------------------------------
#define ROWB 80          // staging row stride (bytes)
#define CSTR 260         // s_comp per-channel stride (floats): conflict-free

__global__ __launch_bounds__(256, 4)
void fv_main(const float* __restrict__ bbox,
             const int* __restrict__ ph,
             const int* __restrict__ pw,
             float* __restrict__ out) {
    __shared__ float sM[NV * 12];
    __shared__ float s_comp[8 * CSTR];
    __shared__ float s_w[NV * 32];
    __shared__ __align__(16) unsigned char sA[NV * 32 * ROWB];

    int tid = threadIdx.x;
    if (tid < 96) sM[tid] = g_M[tid];
    __syncthreads();

    int v    = tid >> 5;       // warp = view
    int lane = tid & 31;       // lane = voxel
    int i = blockIdx.x * 32 + lane;
    int j = blockIdx.y;
    int k = blockIdx.z;

    // ---- projection ----
    float x = (float)i * VOXEL_F + HALF_F + bbox[0];
    float y = (float)j * VOXEL_F + HALF_F + bbox[1];
    float z = (float)k * VOXEL_F + HALF_F + bbox[2];

    const float* M = sM + v * 12;
    float px = M[0] * x + M[1] * y + M[2]  * z + M[3];
    float py = M[4] * x + M[5] * y + M[6]  * z + M[7];
    float pz = M[8] * x + M[9] * y + M[10] * z + M[11];

    float img_wf = (float)(*pw), img_hf = (float)(*ph);
    float u  = px / pz, vv = py / pz;
    float gx = u / img_wf - 1.f, gy = vv / img_hf - 1.f;
    float ix = (gx + 1.f) * 0.5f * (float)(W_F - 1);
    float iy = (gy + 1.f) * 0.5f * (float)(H_F - 1);

    float ix0 = floorf(ix), iy0 = floorf(iy);
    float ax = ix - ix0, ay = iy - iy0;
    float wnw = (1.f - ax) * (1.f - ay);
    float wne = ax * (1.f - ay);
    float wsw = (1.f - ax) * ay;
    float wse = ax * ay;
    float mask = (ix >= 0.f && ix <= (float)(W_F - 1) &&
                  iy >= 0.f && iy <= (float)(H_F - 1) && pz > 0.f) ? 1.f : 0.f;

    int cx0 = (int)fminf(fmaxf(ix0,       0.f), (float)(W_F - 1));
    int cx1 = (int)fminf(fmaxf(ix0 + 1.f, 0.f), (float)(W_F - 1));
    int cy0 = (int)fminf(fmaxf(iy0,       0.f), (float)(H_F - 1));
    int cy1 = (int)fminf(fmaxf(iy0 + 1.f, 0.f), (float)(H_F - 1));

    // base byte offset + pure-IADD corner deltas
    size_t off00 = (size_t)(((v * H_F + cy0) * W_F + cx0)) * 16u;
    int dx = (cx1 - cx0) * 16;            // 0 or 16
    int dy = (cy1 - cy0) * (W_F * 16);    // 0 or 2048

    // prefetch per-view mask-sum (used late)
    float S = g_msum[v * (RESO * RESO) + j * RESO + k];

    __half2 wnwh = __float2half2_rn(wnw);
    __half2 wneh = __float2half2_rn(wne);
    __half2 wswh = __float2half2_rn(wsw);
    __half2 wseh = __float2half2_rn(wse);
    __half2 zeroh = __float2half2_rn(0.f);

    // ---- gather + interp + ReLU -> h1 staging ----
    unsigned char* myrow = sA + (v * 32 + lane) * ROWB;
    const unsigned char* gb = (const unsigned char*)g_Gh + off00;
#pragma unroll
    for (int pp = 0; pp < 4; pp++) {
        const unsigned char* base = gb + (size_t)pp * PLANE_BYTES;
        uint4 a = *(const uint4*)(base);
        uint4 b = *(const uint4*)(base + dx);
        uint4 c = *(const uint4*)(base + dy);
        uint4 d = *(const uint4*)(base + dy + dx);
        const u32* au = &a.x; const u32* bu = &b.x;
        const u32* cu = &c.x; const u32* du = &d.x;
        u32 hq[4];
#pragma unroll
        for (int q = 0; q < 4; q++) {
            __half2 ha = *(const __half2*)&au[q];
            __half2 hb = *(const __half2*)&bu[q];
            __half2 hc = *(const __half2*)&cu[q];
            __half2 hd = *(const __half2*)&du[q];
            __half2 r = __hmul2(wnwh, ha);
            r = __hfma2(wneh, hb, r);
            r = __hfma2(wswh, hc, r);
            r = __hfma2(wseh, hd, r);
            r = __hmax2(r, zeroh);
            hq[q] = *(const u32*)&r;
        }
        ((uint4*)myrow)[pp] = make_uint4(hq[0], hq[1], hq[2], hq[3]);
    }

    int bn = lane >> 2;
    int bk = (lane & 3) * 2;

    __syncwarp();

    // ---- A fragments ----
    u32 abase = (u32)__cvta_generic_to_shared(sA + v * 32 * ROWB);
    u32 laddr = abase + (lane & 15) * ROWB + ((lane >> 4) << 4);
    u32 A[2][2][4];
#pragma unroll
    for (int mt = 0; mt < 2; mt++)
#pragma unroll
        for (int kt = 0; kt < 2; kt++)
            ldsm_x4(A[mt][kt][0], A[mt][kt][1], A[mt][kt][2], A[mt][kt][3],
                    laddr + mt * 16 * ROWB + kt * 32);

    // ---- layer 2 (16 HMMA, hi+lo weight split); fragments from L1 ----
    const uint4* gf = (const uint4*)g_frag;
    float C2[2][2][4];
    {
        uint4 fb2 = gf[5 * 32 + lane];          // b2 biases
#pragma unroll
        for (int mt = 0; mt < 2; mt++) {
            C2[mt][0][0] = __uint_as_float(fb2.x); C2[mt][0][1] = __uint_as_float(fb2.y);
            C2[mt][0][2] = __uint_as_float(fb2.x); C2[mt][0][3] = __uint_as_float(fb2.y);
            C2[mt][1][0] = __uint_as_float(fb2.z); C2[mt][1][1] = __uint_as_float(fb2.w);
            C2[mt][1][2] = __uint_as_float(fb2.z); C2[mt][1][3] = __uint_as_float(fb2.w);
        }
    }
#pragma unroll
    for (int hl = 0; hl < 2; hl++) {            // hi then lo weights
#pragma unroll
        for (int kt = 0; kt < 2; kt++) {
            uint4 fw = gf[(hl * 2 + kt) * 32 + lane];
#pragma unroll
            for (int mt = 0; mt < 2; mt++) {
                mma16816(C2[mt][0], A[mt][kt], fw.x, fw.y);
                mma16816(C2[mt][1], A[mt][kt], fw.z, fw.w);
            }
        }
    }

    // ---- layer 3 (4 HMMA, fragment chaining) ----
    float C3[2][4];
    {
        uint4 f3 = gf[4 * 32 + lane];           // B3 hi (x,y) + lo (z,w)
        uint4 f6 = gf[6 * 32 + lane];           // b3 biases in x,y
        float bb0 = __uint_as_float(f6.x);
        float bb1 = __uint_as_float(f6.y);
#pragma unroll
        for (int mt = 0; mt < 2; mt++) {
            u32 A3[4];
            A3[0] = pack_h2(fmaxf(C2[mt][0][0], 0.f), fmaxf(C2[mt][0][1], 0.f));
            A3[1] = pack_h2(fmaxf(C2[mt][0][2], 0.f), fmaxf(C2[mt][0][3], 0.f));
            A3[2] = pack_h2(fmaxf(C2[mt][1][0], 0.f), fmaxf(C2[mt][1][1], 0.f));
            A3[3] = pack_h2(fmaxf(C2[mt][1][2], 0.f), fmaxf(C2[mt][1][3], 0.f));
            C3[mt][0] = bb0; C3[mt][1] = bb1; C3[mt][2] = bb0; C3[mt][3] = bb1;
            mma16816(C3[mt], A3, f3.x, f3.y);
            mma16816(C3[mt], A3, f3.z, f3.w);
        }
    }

    // ---- weight ----
    float w = mask / (S + 1e-8f);
    s_w[v * 32 + lane] = w;

    // ---- scatter comp to s_comp (padded stride -> conflict-free) ----
#pragma unroll
    for (int mt = 0; mt < 2; mt++) {
        int r0 = (lane >> 2) + mt * 16;
        s_comp[(bk    ) * CSTR + v * 32 + r0    ] = C3[mt][0];
        s_comp[(bk + 1) * CSTR + v * 32 + r0    ] = C3[mt][1];
        s_comp[(bk    ) * CSTR + v * 32 + r0 + 8] = C3[mt][2];
        s_comp[(bk + 1) * CSTR + v * 32 + r0 + 8] = C3[mt][3];
    }

    __syncthreads();

    // ---- cross-view reduction ----
    int vox2 = tid & 31;
    int ch   = tid >> 5;
    float mean = 0.f;
#pragma unroll
    for (int v2 = 0; v2 < NV; v2++)
        mean += s_w[v2 * 32 + vox2] * s_comp[ch * CSTR + v2 * 32 + vox2];
    float var = 0.f;
#pragma unroll
    for (int v2 = 0; v2 < NV; v2++) {
        float d = s_comp[ch * CSTR + v2 * 32 + vox2] - mean;
        var += s_w[v2 * 32 + vox2] * d * d;
    }

    int i_out = blockIdx.x * 32 + vox2;
    out[(( ch      * RESO + k) * RESO + j) * RESO + i_out] = mean;
    out[(((ch + 8) * RESO + k) * RESO + j) * RESO + i_out] = var;
}

// ---------------------------------------------------------------------------
extern "C" void kernel_launch(void* const* d_in, const int* in_sizes, int n_in,
                              void* d_out, int out_size) {
    const float* feats = (const float*)d_in[0];
    const float* poses = (const float*)d_in[1];
    const float* Ks    = (const float*)d_in[2];
    const float* bbox  = (const float*)d_in[3];
    const int*   ph    = (const int*)d_in[4];
    const int*   pw    = (const int*)d_in[5];
    const float* W1 = (const float*)d_in[6];
    const float* b1 = (const float*)d_in[7];
    const float* W2 = (const float*)d_in[8];
    const float* b2 = (const float*)d_in[9];
    const float* W3 = (const float*)d_in[10];
    const float* b3 = (const float*)d_in[11];
    float* out = (float*)d_out;

    prep_kernel<<<GEMM_BLOCKS + MSUM_BLOCKS + 1, 256>>>(
        feats, W1, b1, Ks, poses, bbox, ph, pw, W2, b2, W3, b3);

    dim3 mg(RESO / 32, RESO, RESO);
    fv_main<<<mg, 256>>>(bbox, ph, pw, out);
}

// round 10
// speedup vs baseline: 1.1181x; 1.1181x over previous
#include <cuda_runtime.h>
#include <cuda_fp16.h>

#define NV   8
#define C_CH 32
#define H_F  128
#define W_F  128
#define HW_F (H_F * W_F)
#define RESO 64

#define VOXEL_F ((float)(0.3/64.0))
#define HALF_F  ((float)(0.3/128.0))

typedef unsigned long long u64;
typedef unsigned u32;

// ---- helpers ----
__device__ __forceinline__ u32 pack_h2(float lo, float hi) {
    u32 r; asm("cvt.rn.f16x2.f32 %0, %1, %2;" : "=r"(r) : "f"(hi), "f"(lo)); return r;
}
__device__ __forceinline__ float rhalf(float x) {
    return __half2float(__float2half_rn(x));
}
__device__ __forceinline__ void ldsm_x4(u32& r0, u32& r1, u32& r2, u32& r3, u32 addr) {
    asm volatile("ldmatrix.sync.aligned.m8n8.x4.shared.b16 {%0,%1,%2,%3}, [%4];"
                 : "=r"(r0), "=r"(r1), "=r"(r2), "=r"(r3) : "r"(addr));
}
__device__ __forceinline__ void mma16816(float* c, const u32* a, u32 b0, u32 b1) {
    asm volatile("mma.sync.aligned.m16n8k16.row.col.f32.f16.f16.f32 "
                 "{%0,%1,%2,%3}, {%4,%5,%6,%7}, {%8,%9}, {%0,%1,%2,%3};"
                 : "+f"(c[0]), "+f"(c[1]), "+f"(c[2]), "+f"(c[3])
                 : "r"(a[0]), "r"(a[1]), "r"(a[2]), "r"(a[3]), "r"(b0), "r"(b1));
}

// Scratch
__device__ __align__(16) u32 g_Gh[4 * NV * HW_F * 4];   // fp16 plane-split G
__device__ float g_msum[NV * RESO * RESO];
__device__ __align__(16) u32 g_frag[7 * 32 * 4];        // fv_main per-lane frags
__device__ float g_M[NV * 12];

#define GEMM_BLOCKS 512
#define MSUM_BLOCKS 128
#define ROWB 80

// ---------------------------------------------------------------------------
// Prep kernel: [0,512) HMMA per-pixel GEMM G = feats@W1+b1 (fp16 store);
// [512,640) msum; block 640 = fv_main fragment/M precompute.
// ---------------------------------------------------------------------------
__global__ __launch_bounds__(256, 3)
void prep_kernel(const float* __restrict__ feats,
                 const float* __restrict__ W1,
                 const float* __restrict__ b1,
                 const float* __restrict__ Ks,
                 const float* __restrict__ poses,
                 const float* __restrict__ bbox,
                 const int* __restrict__ ph,
                 const int* __restrict__ pw,
                 const float* __restrict__ W2, const float* __restrict__ b2,
                 const float* __restrict__ W3, const float* __restrict__ b3) {
    int tid = threadIdx.x;
    if (blockIdx.x < GEMM_BLOCKS) {
        // HMMA GEMM: warp = 32 consecutive pixels
        __shared__ __align__(16) uint4 sFragW[8][32];   // [hl*4+kt*2+ntp][lane]
        __shared__ __align__(16) uint4 sFragB[2][32];   // bias frags
        __shared__ __align__(16) unsigned char sStage[8][32 * ROWB];

        int wid  = tid >> 5;
        int lane = tid & 31;
        int p0 = blockIdx.x * 256 + wid * 32;           // warp's first pixel
        int v  = p0 >> 14;
        int pl = p0 & (HW_F - 1);
        const float* fp = feats + (size_t)v * C_CH * HW_F + pl + lane;

        // ---- coalesced channel loads -> fp16 -> staging row ----
        u32 hq[16];
#pragma unroll
        for (int c2 = 0; c2 < 16; c2++) {
            float f0 = fp[(2 * c2    ) * HW_F];
            float f1 = fp[(2 * c2 + 1) * HW_F];
            hq[c2] = pack_h2(f0, f1);
        }
        {
            uint4* myrow = (uint4*)(sStage[wid] + lane * ROWB);
#pragma unroll
            for (int q = 0; q < 4; q++)
                myrow[q] = make_uint4(hq[q*4+0], hq[q*4+1], hq[q*4+2], hq[q*4+3]);
        }

        // ---- warp 0 builds W1/b1 fragments into smem (hi+lo split) ----
        if (wid == 0) {
            int bn  = lane >> 2;
            int bk2 = (lane & 3) * 2;
#pragma unroll
            for (int hl = 0; hl < 2; hl++)
#pragma unroll
                for (int kt = 0; kt < 2; kt++)
#pragma unroll
                    for (int ntp = 0; ntp < 2; ntp++) {
                        uint4 o;
#pragma unroll
                        for (int ii = 0; ii < 2; ii++) {
                            int n  = (ntp * 2 + ii) * 8 + bn;
                            int k0 = kt * 16 + bk2;
                            float w0 = W1[(k0    ) * 32 + n];
                            float w1 = W1[(k0 + 1) * 32 + n];
                            float w8 = W1[(k0 + 8) * 32 + n];
                            float w9 = W1[(k0 + 9) * 32 + n];
                            u32 r0, r1;
                            if (hl == 0) {
                                r0 = pack_h2(w0, w1); r1 = pack_h2(w8, w9);
                            } else {
                                r0 = pack_h2(w0 - rhalf(w0), w1 - rhalf(w1));
                                r1 = pack_h2(w8 - rhalf(w8), w9 - rhalf(w9));
                            }
                            if (ii == 0) { o.x = r0; o.y = r1; }
                            else         { o.z = r0; o.w = r1; }
                        }
                        sFragW[hl * 4 + kt * 2 + ntp][lane] = o;
                    }
#pragma unroll
            for (int ntp = 0; ntp < 2; ntp++) {
                uint4 ob;
                ob.x = __float_as_uint(b1[ntp * 16     + bk2]);
                ob.y = __float_as_uint(b1[ntp * 16     + bk2 + 1]);
                ob.z = __float_as_uint(b1[ntp * 16 + 8 + bk2]);
                ob.w = __float_as_uint(b1[ntp * 16 + 8 + bk2 + 1]);
                sFragB[ntp][lane] = ob;
            }
        }
        __syncthreads();

        // ---- A fragments ----
        u32 abase = (u32)__cvta_generic_to_shared(sStage[wid]);
        u32 laddr = abase + (lane & 15) * ROWB + ((lane >> 4) << 4);
        u32 A[2][2][4];
#pragma unroll
        for (int mt = 0; mt < 2; mt++)
#pragma unroll
            for (int kt = 0; kt < 2; kt++)
                ldsm_x4(A[mt][kt][0], A[mt][kt][1], A[mt][kt][2], A[mt][kt][3],
                        laddr + mt * 16 * ROWB + kt * 32);

        // ---- C init from bias ----
        float C[2][4][4];
#pragma unroll
        for (int ntp = 0; ntp < 2; ntp++) {
            uint4 ob = sFragB[ntp][lane];
#pragma unroll
            for (int ii = 0; ii < 2; ii++) {
                int nt = ntp * 2 + ii;
                float bb0 = __uint_as_float(ii ? ob.z : ob.x);
                float bb1 = __uint_as_float(ii ? ob.w : ob.y);
#pragma unroll
                for (int mt = 0; mt < 2; mt++) {
                    C[mt][nt][0] = bb0; C[mt][nt][1] = bb1;
                    C[mt][nt][2] = bb0; C[mt][nt][3] = bb1;
                }
            }
        }

        // ---- 32 HMMA ----
#pragma unroll
        for (int hl = 0; hl < 2; hl++)
#pragma unroll
            for (int kt = 0; kt < 2; kt++)
#pragma unroll
                for (int ntp = 0; ntp < 2; ntp++) {
                    uint4 fw = sFragW[hl * 4 + kt * 2 + ntp][lane];
#pragma unroll
                    for (int mt = 0; mt < 2; mt++) {
                        mma16816(C[mt][ntp * 2 + 0], A[mt][kt], fw.x, fw.y);
                        mma16816(C[mt][ntp * 2 + 1], A[mt][kt], fw.z, fw.w);
                    }
                }

        __syncwarp();
        // ---- epilogue: restage C as fp16 pixel rows (conflict-free) ----
#pragma unroll
        for (int mt = 0; mt < 2; mt++)
#pragma unroll
            for (int nt = 0; nt < 4; nt++) {
                u32 h01 = pack_h2(C[mt][nt][0], C[mt][nt][1]);
                u32 h23 = pack_h2(C[mt][nt][2], C[mt][nt][3]);
                int r0   = mt * 16 + (lane >> 2);
                int colb = nt * 16 + (lane & 3) * 4;
                *(u32*)(sStage[wid] + r0 * ROWB + colb)       = h01;
                *(u32*)(sStage[wid] + (r0 + 8) * ROWB + colb) = h23;
            }
        __syncwarp();

        // ---- coalesced plane-split store ----
        const uint4* grow = (const uint4*)(sStage[wid] + lane * ROWB);
        uint4* gbase = (uint4*)g_Gh;
#pragma unroll
        for (int pp = 0; pp < 4; pp++)
            gbase[(size_t)pp * (NV * HW_F) + p0 + lane] = grow[pp];

    } else if (blockIdx.x < GEMM_BLOCKS + MSUM_BLOCKS) {
        int idx = (blockIdx.x - GEMM_BLOCKS) * 256 + tid;   // 0..32767
        int k = idx & 63, j = (idx >> 6) & 63, v = idx >> 12;

        const float* K = Ks + v * 9;
        const float* P = poses + v * 12;
        float M[12];
#pragma unroll
        for (int r = 0; r < 3; r++)
#pragma unroll
            for (int c = 0; c < 4; c++)
                M[r * 4 + c] = K[r * 3 + 0] * P[0 * 4 + c] +
                               K[r * 3 + 1] * P[1 * 4 + c] +
                               K[r * 3 + 2] * P[2 * 4 + c];

        float img_wf = (float)(*pw), img_hf = (float)(*ph);
        float y = (float)j * VOXEL_F + HALF_F + bbox[1];
        float z = (float)k * VOXEL_F + HALF_F + bbox[2];

        float s = 0.f;
        for (int i = 0; i < RESO; i++) {
            float x  = (float)i * VOXEL_F + HALF_F + bbox[0];
            float px = M[0] * x + M[1] * y + M[2]  * z + M[3];
            float py = M[4] * x + M[5] * y + M[6]  * z + M[7];
            float pz = M[8] * x + M[9] * y + M[10] * z + M[11];
            float u  = px / pz, vv = py / pz;
            float gx = u / img_wf - 1.f, gy = vv / img_hf - 1.f;
            float ix = (gx + 1.f) * 0.5f * (float)(W_F - 1);
            float iy = (gy + 1.f) * 0.5f * (float)(H_F - 1);
            float m = (ix >= 0.f && ix <= (float)(W_F - 1) &&
                       iy >= 0.f && iy <= (float)(H_F - 1) && pz > 0.f) ? 1.f : 0.f;
            s += m;
        }
        g_msum[idx] = s;
    } else {
        // fv_main fragment + M precompute
        if (tid < 32) {
            int lane = tid;
            int bn = lane >> 2;
            int bk = (lane & 3) * 2;
            u32 fr[28];
#pragma unroll
            for (int kt = 0; kt < 2; kt++)
#pragma unroll
                for (int nt = 0; nt < 2; nt++) {
                    int n = bn + nt * 8;
                    int k0 = bk + kt * 16;
                    float w0 = W2[(k0    ) * 16 + n];
                    float w1 = W2[(k0 + 1) * 16 + n];
                    float w8 = W2[(k0 + 8) * 16 + n];
                    float w9 = W2[(k0 + 9) * 16 + n];
                    fr[    kt * 4 + nt * 2 + 0] = pack_h2(w0, w1);
                    fr[    kt * 4 + nt * 2 + 1] = pack_h2(w8, w9);
                    fr[8 + kt * 4 + nt * 2 + 0] = pack_h2(w0 - rhalf(w0), w1 - rhalf(w1));
                    fr[8 + kt * 4 + nt * 2 + 1] = pack_h2(w8 - rhalf(w8), w9 - rhalf(w9));
                }
            {
                float w0 = W3[(bk    ) * 8 + bn];
                float w1 = W3[(bk + 1) * 8 + bn];
                float w8 = W3[(bk + 8) * 8 + bn];
                float w9 = W3[(bk + 9) * 8 + bn];
                fr[16] = pack_h2(w0, w1);
                fr[17] = pack_h2(w8, w9);
                fr[18] = pack_h2(w0 - rhalf(w0), w1 - rhalf(w1));
                fr[19] = pack_h2(w8 - rhalf(w8), w9 - rhalf(w9));
            }
            fr[20] = __float_as_uint(b2[bk]);
            fr[21] = __float_as_uint(b2[bk + 1]);
            fr[22] = __float_as_uint(b2[8 + bk]);
            fr[23] = __float_as_uint(b2[8 + bk + 1]);
            fr[24] = __float_as_uint(b3[bk]);
            fr[25] = __float_as_uint(b3[bk + 1]);
            fr[26] = 0; fr[27] = 0;
#pragma unroll
            for (int c4 = 0; c4 < 7; c4++)
#pragma unroll
                for (int r = 0; r < 4; r++)
                    g_frag[(c4 * 32 + tid) * 4 + r] = fr[c4 * 4 + r];
        } else if (tid >= 32 && tid < 128 + 32) {
            int e = tid - 32;
            if (e < 96) {
                int v = e / 12, q = e % 12, r = q >> 2, c = q & 3;
                const float* K = Ks + v * 9;
                const float* P = poses + v * 12;
                g_M[e] = K[r * 3 + 0] * P[0 + c] + K[r * 3 + 1] * P[4 + c] +
                         K[r * 3 + 2] * P[8 + c];
            }
        }
    }
}

// ---------------------------------------------------------------------------
// Main fused kernel (R8 version — best measured).
// ---------------------------------------------------------------------------
#define CSTR 260

__global__ __launch_bounds__(256, 4)
void fv_main(const float* __restrict__ bbox,
             const int* __restrict__ ph,
             const int* __restrict__ pw,
             float* __restrict__ out) {
    __shared__ float sM[NV * 12];
    __shared__ float s_comp[8 * CSTR];
    __shared__ float s_w[NV * 32];
    __shared__ __align__(16) unsigned char sA[NV * 32 * ROWB];

    int tid = threadIdx.x;
    if (tid < 96) sM[tid] = g_M[tid];
    __syncthreads();

    int v    = tid >> 5;
    int lane = tid & 31;
    int i = blockIdx.x * 32 + lane;
    int j = blockIdx.y;
    int k = blockIdx.z;

    float x = (float)i * VOXEL_F + HALF_F + bbox[0];
    float y = (float)j * VOXEL_F + HALF_F + bbox[1];
    float z = (float)k * VOXEL_F + HALF_F + bbox[2];

    const float* M = sM + v * 12;
    float px = M[0] * x + M[1] * y + M[2]  * z + M[3];
    float py = M[4] * x + M[5] * y + M[6]  * z + M[7];
    float pz = M[8] * x + M[9] * y + M[10] * z + M[11];

    float img_wf = (float)(*pw), img_hf = (float)(*ph);
    float u  = px / pz, vv = py / pz;
    float gx = u / img_wf - 1.f, gy = vv / img_hf - 1.f;
    float ix = (gx + 1.f) * 0.5f * (float)(W_F - 1);
    float iy = (gy + 1.f) * 0.5f * (float)(H_F - 1);

    float ix0 = floorf(ix), iy0 = floorf(iy);
    float ax = ix - ix0, ay = iy - iy0;
    float wnw = (1.f - ax) * (1.f - ay);
    float wne = ax * (1.f - ay);
    float wsw = (1.f - ax) * ay;
    float wse = ax * ay;
    float mask = (ix >= 0.f && ix <= (float)(W_F - 1) &&
                  iy >= 0.f && iy <= (float)(H_F - 1) && pz > 0.f) ? 1.f : 0.f;

    int cx0 = (int)fminf(fmaxf(ix0,       0.f), (float)(W_F - 1));
    int cx1 = (int)fminf(fmaxf(ix0 + 1.f, 0.f), (float)(W_F - 1));
    int cy0 = (int)fminf(fmaxf(iy0,       0.f), (float)(H_F - 1));
    int cy1 = (int)fminf(fmaxf(iy0 + 1.f, 0.f), (float)(H_F - 1));

    int p00 = (v * H_F + cy0) * W_F + cx0;
    int p01 = (v * H_F + cy0) * W_F + cx1;
    int p10 = (v * H_F + cy1) * W_F + cx0;
    int p11 = (v * H_F + cy1) * W_F + cx1;

    __half2 wnwh = __float2half2_rn(wnw);
    __half2 wneh = __float2half2_rn(wne);
    __half2 wswh = __float2half2_rn(wsw);
    __half2 wseh = __float2half2_rn(wse);
    __half2 zeroh = __float2half2_rn(0.f);

    unsigned char* myrow = sA + (v * 32 + lane) * ROWB;
    const uint4* gbase = (const uint4*)g_Gh;
#pragma unroll
    for (int pp = 0; pp < 4; pp++) {
        const uint4* plane = gbase + (size_t)pp * (NV * HW_F);
        uint4 a = plane[p00], b = plane[p01], c = plane[p10], d = plane[p11];
        const u32* au = &a.x; const u32* bu = &b.x;
        const u32* cu = &c.x; const u32* du = &d.x;
        u32 hq[4];
#pragma unroll
        for (int q = 0; q < 4; q++) {
            __half2 ha = *(const __half2*)&au[q];
            __half2 hb = *(const __half2*)&bu[q];
            __half2 hc = *(const __half2*)&cu[q];
            __half2 hd = *(const __half2*)&du[q];
            __half2 r = __hmul2(wnwh, ha);
            r = __hfma2(wneh, hb, r);
            r = __hfma2(wswh, hc, r);
            r = __hfma2(wseh, hd, r);
            r = __hmax2(r, zeroh);
            hq[q] = *(const u32*)&r;
        }
        ((uint4*)myrow)[pp] = make_uint4(hq[0], hq[1], hq[2], hq[3]);
    }

    int bk = (lane & 3) * 2;

    __syncwarp();

    u32 abase = (u32)__cvta_generic_to_shared(sA + v * 32 * ROWB);
    u32 laddr = abase + (lane & 15) * ROWB + ((lane >> 4) << 4);
    u32 A[2][2][4];
#pragma unroll
    for (int mt = 0; mt < 2; mt++)
#pragma unroll
        for (int kt = 0; kt < 2; kt++)
            ldsm_x4(A[mt][kt][0], A[mt][kt][1], A[mt][kt][2], A[mt][kt][3],
                    laddr + mt * 16 * ROWB + kt * 32);

    const uint4* gf = (const uint4*)g_frag;
    float C2[2][2][4];
    {
        uint4 fb2 = gf[5 * 32 + lane];
#pragma unroll
        for (int mt = 0; mt < 2; mt++) {
            C2[mt][0][0] = __uint_as_float(fb2.x); C2[mt][0][1] = __uint_as_float(fb2.y);
            C2[mt][0][2] = __uint_as_float(fb2.x); C2[mt][0][3] = __uint_as_float(fb2.y);
            C2[mt][1][0] = __uint_as_float(fb2.z); C2[mt][1][1] = __uint_as_float(fb2.w);
            C2[mt][1][2] = __uint_as_float(fb2.z); C2[mt][1][3] = __uint_as_float(fb2.w);
        }
    }
#pragma unroll
    for (int hl = 0; hl < 2; hl++) {
#pragma unroll
        for (int kt = 0; kt < 2; kt++) {
            uint4 fw = gf[(hl * 2 + kt) * 32 + lane];
#pragma unroll
            for (int mt = 0; mt < 2; mt++) {
                mma16816(C2[mt][0], A[mt][kt], fw.x, fw.y);
                mma16816(C2[mt][1], A[mt][kt], fw.z, fw.w);
            }
        }
    }

    float C3[2][4];
    {
        uint4 f3 = gf[4 * 32 + lane];
        uint4 f6 = gf[6 * 32 + lane];
        float bb0 = __uint_as_float(f6.x);
        float bb1 = __uint_as_float(f6.y);
#pragma unroll
        for (int mt = 0; mt < 2; mt++) {
            u32 A3[4];
            A3[0] = pack_h2(fmaxf(C2[mt][0][0], 0.f), fmaxf(C2[mt][0][1], 0.f));
            A3[1] = pack_h2(fmaxf(C2[mt][0][2], 0.f), fmaxf(C2[mt][0][3], 0.f));
            A3[2] = pack_h2(fmaxf(C2[mt][1][0], 0.f), fmaxf(C2[mt][1][1], 0.f));
            A3[3] = pack_h2(fmaxf(C2[mt][1][2], 0.f), fmaxf(C2[mt][1][3], 0.f));
            C3[mt][0] = bb0; C3[mt][1] = bb1; C3[mt][2] = bb0; C3[mt][3] = bb1;
            mma16816(C3[mt], A3, f3.x, f3.y);
            mma16816(C3[mt], A3, f3.z, f3.w);
        }
    }

    float S = g_msum[v * (RESO * RESO) + j * RESO + k];
    float w = mask / (S + 1e-8f);
    s_w[v * 32 + lane] = w;

#pragma unroll
    for (int mt = 0; mt < 2; mt++) {
        int r0 = (lane >> 2) + mt * 16;
        s_comp[(bk    ) * CSTR + v * 32 + r0    ] = C3[mt][0];
        s_comp[(bk + 1) * CSTR + v * 32 + r0    ] = C3[mt][1];
        s_comp[(bk    ) * CSTR + v * 32 + r0 + 8] = C3[mt][2];
        s_comp[(bk + 1) * CSTR + v * 32 + r0 + 8] = C3[mt][3];
    }

    __syncthreads();

    int vox2 = tid & 31;
    int ch   = tid >> 5;
    float mean = 0.f;
#pragma unroll
    for (int v2 = 0; v2 < NV; v2++)
        mean += s_w[v2 * 32 + vox2] * s_comp[ch * CSTR + v2 * 32 + vox2];
    float var = 0.f;
#pragma unroll
    for (int v2 = 0; v2 < NV; v2++) {
        float d = s_comp[ch * CSTR + v2 * 32 + vox2] - mean;
        var += s_w[v2 * 32 + vox2] * d * d;
    }

    int i_out = blockIdx.x * 32 + vox2;
    out[(( ch      * RESO + k) * RESO + j) * RESO + i_out] = mean;
    out[(((ch + 8) * RESO + k) * RESO + j) * RESO + i_out] = var;
}

// ---------------------------------------------------------------------------
extern "C" void kernel_launch(void* const* d_in, const int* in_sizes, int n_in,
                              void* d_out, int out_size) {
    const float* feats = (const float*)d_in[0];
    const float* poses = (const float*)d_in[1];
    const float* Ks    = (const float*)d_in[2];
    const float* bbox  = (const float*)d_in[3];
    const int*   ph    = (const int*)d_in[4];
    const int*   pw    = (const int*)d_in[5];
    const float* W1 = (const float*)d_in[6];
    const float* b1 = (const float*)d_in[7];
    const float* W2 = (const float*)d_in[8];
    const float* b2 = (const float*)d_in[9];
    const float* W3 = (const float*)d_in[10];
    const float* b3 = (const float*)d_in[11];
    float* out = (float*)d_out;

    prep_kernel<<<GEMM_BLOCKS + MSUM_BLOCKS + 1, 256>>>(
        feats, W1, b1, Ks, poses, bbox, ph, pw, W2, b2, W3, b3);

    dim3 mg(RESO / 32, RESO, RESO);
    fv_main<<<mg, 256>>>(bbox, ph, pw, out);
}